// round 12
// baseline (speedup 1.0000x reference)
#include <cuda_runtime.h>

// SSIM, fully fused, single kernel. X,Y: f32[32,3,512,512] -> scalar mean SSIM.
//
// R11 + phase-2 reshape: 8 vrows x 1 col per thread. 18 taps x 20B loads
// (mu u64 + sq u64 + xy f32) = 360B/thread vs 560B for 4x2 -- -36% LDS bytes,
// identical fma work and accumulator count.
// TW=32 x TH=64, smem planes mu u64[74][32] {hx,hy}, sq u64[74][32] {hxx,hyy},
// xy f32[74][32] = 47.36KB -> 4 CTAs/SM, 64 regs/thread. Static smem offsets.
// Phase 1 (8 col-quads x 32 rows): horizontal 11-tap Gaussian, scalar FFMA-imm
//   (rt=1); map pairs packed only at the smem store.
// Phase 2 (32 cols x 8 row-groups): vertical 11-tap conv, fma2 for the packed
//   map-pairs + FFMA-imm for xy.
// Epilogue folds [-1,1]->[0,1]: mu' = (mu+1)/2, sigma' = sigma/4.
// Block partials -> __device__ array; last block reduces, writes scalar, resets.

#define TW 32
#define TH 64
#define NHR (TH + 10)   // 74
#define NTHR 256
#define GX 16
#define GY 8
#define GZ 96
#define NBLOCKS (GX * GY * GZ)

#define MU_OFF 0
#define SQ_OFF (NHR * TW * 8)                         // 18944
#define XY_OFF (2 * NHR * TW * 8)                     // 37888
#define SMEM_BYTES (2 * NHR * TW * 8 + NHR * TW * 4)  // 47360

typedef unsigned long long u64;

__device__ float g_partials[NBLOCKS];
__device__ unsigned int g_count = 0;

// scalar: acc += v * w[k], w[k] immediate multiplier (FFMA-imm, rt=1).
__device__ __forceinline__ void fmaw(const int k, const float v, float& a) {
    switch (k) {
    case 0:  asm("fma.rn.f32 %0, %1, 0f3A86CAB5, %0;" : "+f"(a) : "f"(v)); break;
    case 1:  asm("fma.rn.f32 %0, %1, 0f3BF8FF05, %0;" : "+f"(a) : "f"(v)); break;
    case 2:  asm("fma.rn.f32 %0, %1, 0f3D137590, %0;" : "+f"(a) : "f"(v)); break;
    case 3:  asm("fma.rn.f32 %0, %1, 0f3DDFF883, %0;" : "+f"(a) : "f"(v)); break;
    case 4:  asm("fma.rn.f32 %0, %1, 0f3E5A1E20, %0;" : "+f"(a) : "f"(v)); break;
    case 5:  asm("fma.rn.f32 %0, %1, 0f3E8832B1, %0;" : "+f"(a) : "f"(v)); break;
    case 6:  asm("fma.rn.f32 %0, %1, 0f3E5A1E20, %0;" : "+f"(a) : "f"(v)); break;
    case 7:  asm("fma.rn.f32 %0, %1, 0f3DDFF883, %0;" : "+f"(a) : "f"(v)); break;
    case 8:  asm("fma.rn.f32 %0, %1, 0f3D137590, %0;" : "+f"(a) : "f"(v)); break;
    case 9:  asm("fma.rn.f32 %0, %1, 0f3BF8FF05, %0;" : "+f"(a) : "f"(v)); break;
    case 10: asm("fma.rn.f32 %0, %1, 0f3A86CAB5, %0;" : "+f"(a) : "f"(v)); break;
    default: break;
    }
}

__device__ __forceinline__ u64 pk2(float lo, float hi) {
    u64 r;
    asm("mov.b64 %0, {%1, %2};" : "=l"(r) : "f"(lo), "f"(hi));
    return r;
}
__device__ __forceinline__ void upk2(float& lo, float& hi, u64 v) {
    asm("mov.b64 {%0, %1}, %2;" : "=f"(lo), "=f"(hi) : "l"(v));
}
__device__ __forceinline__ u64 fma2(u64 a, u64 b, u64 c) {
    u64 d;
    asm("fma.rn.f32x2 %0, %1, %2, %3;" : "=l"(d) : "l"(a), "l"(b), "l"(c));
    return d;
}

// Gaussian(11, sigma=1.5) weights.
__device__ __host__ __forceinline__ constexpr float gwe(int k) {
    return (k == 0 || k == 10) ? 0.00102838f
         : (k == 1 || k == 9)  ? 0.00759876f
         : (k == 2 || k == 8)  ? 0.03600079f
         : (k == 3 || k == 7)  ? 0.10936072f
         : (k == 4 || k == 6)  ? 0.21300555f
         : (k == 5)            ? 0.26601173f
         : 0.0f;
}

__global__ void __launch_bounds__(NTHR, 4)
ssim_main_kernel(const float* __restrict__ X, const float* __restrict__ Y,
                 float* __restrict__ out, double inv_count) {
    extern __shared__ char shb[];
    u64*   sh_mu = reinterpret_cast<u64*>(shb + MU_OFF);   // [NHR][TW] {hx,hy}
    u64*   sh_sq = reinterpret_cast<u64*>(shb + SQ_OFF);   // [NHR][TW] {hxx,hyy}
    float* sh_xy = reinterpret_cast<float*>(shb + XY_OFF); // [NHR][TW] hxy

    const int tid = threadIdx.x;
    const int c0 = blockIdx.x * TW;
    const int r0 = blockIdx.y * TH;
    const long img = blockIdx.z;
    const float* __restrict__ Xi = X + img * (512L * 512L);
    const float* __restrict__ Yi = Y + img * (512L * 512L);

    // ---------------- Phase 1: horizontal pass (pure scalar FFMA-imm) -----------
    // Map A: 8 col-quads x 32 rows.
    {
        const int q1 = tid & 7;
        const int r1 = tid >> 3;
        const int basec = c0 + 4 * q1;
        for (int hr = r1; hr < NHR; hr += 32) {
            const int gr = r0 + hr;
            const float* __restrict__ xr = Xi + (long)gr * 512;
            const float* __restrict__ yr = Yi + (long)gr * 512;
            const bool rok = (gr < 512);
            float xv[16], yv[16];
#pragma unroll
            for (int q = 0; q < 4; q++) {
                const int qc = basec + 4 * q;
                float4 xq, yq;
                if (rok && qc < 512) {
                    xq = *reinterpret_cast<const float4*>(xr + qc);
                    yq = *reinterpret_cast<const float4*>(yr + qc);
                } else {
                    xq = make_float4(0.f, 0.f, 0.f, 0.f);
                    yq = make_float4(0.f, 0.f, 0.f, 0.f);
                }
                xv[4 * q + 0] = xq.x; xv[4 * q + 1] = xq.y;
                xv[4 * q + 2] = xq.z; xv[4 * q + 3] = xq.w;
                yv[4 * q + 0] = yq.x; yv[4 * q + 1] = yq.y;
                yv[4 * q + 2] = yq.z; yv[4 * q + 3] = yq.w;
            }
            float ax[4], ay[4], axx[4], ayy[4], axy[4];
#pragma unroll
            for (int j = 0; j < 4; j++) {
                ax[j] = 0.f; ay[j] = 0.f; axx[j] = 0.f; ayy[j] = 0.f; axy[j] = 0.f;
            }
#pragma unroll
            for (int t = 0; t < 14; t++) {
                const float xt = xv[t], yt = yv[t];
                const float pxx = xt * xt;
                const float pyy = yt * yt;
                const float pxy = xt * yt;
#pragma unroll
                for (int j = 0; j < 4; j++) {
                    const int k = t - j;
                    if (k >= 0 && k <= 10) {
                        fmaw(k, xt,  ax[j]);
                        fmaw(k, yt,  ay[j]);
                        fmaw(k, pxx, axx[j]);
                        fmaw(k, pyy, ayy[j]);
                        fmaw(k, pxy, axy[j]);
                    }
                }
            }
            // Pair at store time only: {hx,hy} and {hxx,hyy} interleaved planes.
            const int so = hr * TW + 4 * q1;
            *reinterpret_cast<ulonglong2*>(&sh_mu[so]) =
                make_ulonglong2(pk2(ax[0], ay[0]), pk2(ax[1], ay[1]));
            *reinterpret_cast<ulonglong2*>(&sh_mu[so + 2]) =
                make_ulonglong2(pk2(ax[2], ay[2]), pk2(ax[3], ay[3]));
            *reinterpret_cast<ulonglong2*>(&sh_sq[so]) =
                make_ulonglong2(pk2(axx[0], ayy[0]), pk2(axx[1], ayy[1]));
            *reinterpret_cast<ulonglong2*>(&sh_sq[so + 2]) =
                make_ulonglong2(pk2(axx[2], ayy[2]), pk2(axx[3], ayy[3]));
            *reinterpret_cast<float4*>(&sh_xy[so]) =
                make_float4(axy[0], axy[1], axy[2], axy[3]);
        }
    }
    __syncthreads();

    // ---------------- Phase 2: vertical conv, 8 vrows x 1 col, 20B per tap ------
    // Map B: 32 cols x 8 row-groups (8 vrows each).
    const int col = tid & 31;
    const int ty2 = tid >> 5;        // 0..7
    const int lr0 = ty2 * 8;         // 8 * 8 = 64 rows

    u64 WB[6];
#pragma unroll
    for (int k = 0; k < 6; k++) WB[k] = pk2(gwe(k), gwe(k));

    u64 amu[8], asq[8];
    float axy[8];
#pragma unroll
    for (int v = 0; v < 8; v++) { amu[v] = 0ull; asq[v] = 0ull; axy[v] = 0.f; }

#pragma unroll
    for (int i = 0; i < 18; i++) {   // i = v + k, v in 0..7, k in 0..10
        const int roff = (lr0 + i) * TW + col;
        const u64 dm = sh_mu[roff];
        const u64 ds = sh_sq[roff];
        const float dx = sh_xy[roff];
#pragma unroll
        for (int v = 0; v < 8; v++) {
            const int k = i - v;
            if (k >= 0 && k <= 10) {
                const u64 w = WB[k <= 5 ? k : 10 - k];
                amu[v] = fma2(dm, w, amu[v]);
                asq[v] = fma2(ds, w, asq[v]);
                fmaw(k, dx, axy[v]);
            }
        }
    }

    // ---------------- Epilogue + reduction ----------------
    float lsum = 0.0f;
    const float C1 = 1e-4f;      // (0.01)^2
    const float C2x4 = 0.0036f;  // 4*(0.03)^2
    const int ocol = c0 + col;
    const bool cok = (ocol < 502);
#pragma unroll
    for (int v = 0; v < 8; v++) {
        const int orow = r0 + lr0 + v;
        float m1, m2, xx, yy;
        upk2(m1, m2, amu[v]);
        upk2(xx, yy, asq[v]);
        const float xy = axy[v];
        const float s1  = fmaf(-m1, m1, xx);
        const float s2  = fmaf(-m2, m2, yy);
        const float s12 = fmaf(-m1, m2, xy);
        const float m1p = fmaf(0.5f, m1, 0.5f);
        const float m2p = fmaf(0.5f, m2, 0.5f);
        const float csn = fmaf(2.0f, s12, C2x4);
        const float csd = s1 + s2 + C2x4;
        const float t = m1p * m2p;
        const float ln = fmaf(2.0f, t, C1);
        const float ld = fmaf(m1p, m1p, fmaf(m2p, m2p, C1));
        const float ssim = (csn * ln) * __fdividef(1.0f, csd * ld);
        lsum += (cok && orow < 502) ? ssim : 0.0f;
    }

#pragma unroll
    for (int off = 16; off > 0; off >>= 1)
        lsum += __shfl_xor_sync(0xffffffffu, lsum, off);

    __shared__ float wsum[8];
    __shared__ bool is_last;
    const int wid = tid >> 5;
    const int lid = tid & 31;
    if (lid == 0) wsum[wid] = lsum;
    __syncthreads();
    if (tid == 0) {
        float b = 0.0f;
#pragma unroll
        for (int w = 0; w < 8; w++) b += wsum[w];
        const int bi = blockIdx.x + gridDim.x * (blockIdx.y + gridDim.y * blockIdx.z);
        g_partials[bi] = b;
        __threadfence();
        const unsigned int n = atomicAdd(&g_count, 1u);
        is_last = (n == (unsigned int)(NBLOCKS - 1));
    }
    __syncthreads();

    if (is_last) {
        __threadfence();
        double s = 0.0;
        for (int i = tid; i < NBLOCKS; i += NTHR)
            s += (double)g_partials[i];
#pragma unroll
        for (int off = 16; off > 0; off >>= 1)
            s += __shfl_xor_sync(0xffffffffu, s, off);
        __shared__ double sd[8];
        if (lid == 0) sd[wid] = s;
        __syncthreads();
        if (tid == 0) {
            double tot = 0.0;
#pragma unroll
            for (int w = 0; w < 8; w++) tot += sd[w];
            out[0] = (float)(tot * inv_count);
            g_count = 0;  // reset for next graph replay
        }
    }
}

extern "C" void kernel_launch(void* const* d_in, const int* in_sizes, int n_in,
                              void* d_out, int out_size) {
    const float* X = (const float*)d_in[0];
    const float* Y = (const float*)d_in[1];
    float* out = (float*)d_out;

    const int images = in_sizes[0] / (512 * 512);  // 96
    const double count = (double)images * 502.0 * 502.0;

    cudaFuncSetAttribute(ssim_main_kernel,
                         cudaFuncAttributeMaxDynamicSharedMemorySize, SMEM_BYTES);

    dim3 grid(GX, GY, images);  // 16 x 8 x 96 = 12288 blocks
    ssim_main_kernel<<<grid, NTHR, SMEM_BYTES>>>(X, Y, out, 1.0 / count);
}

// round 13
// speedup vs baseline: 1.0567x; 1.0567x over previous
#include <cuda_runtime.h>

// SSIM, fully fused, single kernel. X,Y: f32[32,3,512,512] -> scalar mean SSIM.
//
// R11 (best: 158.4us) + statically peeled phase-1 row iterations so ptxas can
// software-pipeline the next iteration's LDGs under the current FMA body.
// TW=32 x TH=64, smem planes mu u64[74][32] {hx,hy}, sq u64[74][32] {hxx,hyy},
// xy f32[74][32] = 47.36KB -> 4 CTAs/SM (32 warps), 64 regs/thread.
// Phase 1 (8 col-quads x 32 rows, 2 unconditional iters + 1 predicated):
//   horizontal 11-tap Gaussian, scalar FFMA-imm (rt=1); pairs packed at store.
// Phase 2 (16 col-pairs x 16 row-groups, 4 vrows x 2 cols): vertical conv,
//   3 LDS/tap (2x LDS.128 + 1x LDS.64), all fma.rn.f32x2, static offsets.
// Epilogue folds [-1,1]->[0,1]: mu' = (mu+1)/2, sigma' = sigma/4.
// Block partials -> __device__ array; last block reduces, writes scalar, resets.

#define TW 32
#define TH 64
#define NHR (TH + 10)   // 74
#define NTHR 256
#define GX 16
#define GY 8
#define GZ 96
#define NBLOCKS (GX * GY * GZ)

#define MU_OFF 0
#define SQ_OFF (NHR * TW * 8)                         // 18944
#define XY_OFF (2 * NHR * TW * 8)                     // 37888
#define SMEM_BYTES (2 * NHR * TW * 8 + NHR * TW * 4)  // 47360

typedef unsigned long long u64;

__device__ float g_partials[NBLOCKS];
__device__ unsigned int g_count = 0;

// scalar: acc += v * w[k], w[k] immediate multiplier (FFMA-imm, rt=1).
__device__ __forceinline__ void fmaw(const int k, const float v, float& a) {
    switch (k) {
    case 0:  asm("fma.rn.f32 %0, %1, 0f3A86CAB5, %0;" : "+f"(a) : "f"(v)); break;
    case 1:  asm("fma.rn.f32 %0, %1, 0f3BF8FF05, %0;" : "+f"(a) : "f"(v)); break;
    case 2:  asm("fma.rn.f32 %0, %1, 0f3D137590, %0;" : "+f"(a) : "f"(v)); break;
    case 3:  asm("fma.rn.f32 %0, %1, 0f3DDFF883, %0;" : "+f"(a) : "f"(v)); break;
    case 4:  asm("fma.rn.f32 %0, %1, 0f3E5A1E20, %0;" : "+f"(a) : "f"(v)); break;
    case 5:  asm("fma.rn.f32 %0, %1, 0f3E8832B1, %0;" : "+f"(a) : "f"(v)); break;
    case 6:  asm("fma.rn.f32 %0, %1, 0f3E5A1E20, %0;" : "+f"(a) : "f"(v)); break;
    case 7:  asm("fma.rn.f32 %0, %1, 0f3DDFF883, %0;" : "+f"(a) : "f"(v)); break;
    case 8:  asm("fma.rn.f32 %0, %1, 0f3D137590, %0;" : "+f"(a) : "f"(v)); break;
    case 9:  asm("fma.rn.f32 %0, %1, 0f3BF8FF05, %0;" : "+f"(a) : "f"(v)); break;
    case 10: asm("fma.rn.f32 %0, %1, 0f3A86CAB5, %0;" : "+f"(a) : "f"(v)); break;
    default: break;
    }
}

__device__ __forceinline__ u64 pk2(float lo, float hi) {
    u64 r;
    asm("mov.b64 %0, {%1, %2};" : "=l"(r) : "f"(lo), "f"(hi));
    return r;
}
__device__ __forceinline__ void upk2(float& lo, float& hi, u64 v) {
    asm("mov.b64 {%0, %1}, %2;" : "=f"(lo), "=f"(hi) : "l"(v));
}
__device__ __forceinline__ u64 fma2(u64 a, u64 b, u64 c) {
    u64 d;
    asm("fma.rn.f32x2 %0, %1, %2, %3;" : "=l"(d) : "l"(a), "l"(b), "l"(c));
    return d;
}

// Gaussian(11, sigma=1.5) weights.
__device__ __host__ __forceinline__ constexpr float gwe(int k) {
    return (k == 0 || k == 10) ? 0.00102838f
         : (k == 1 || k == 9)  ? 0.00759876f
         : (k == 2 || k == 8)  ? 0.03600079f
         : (k == 3 || k == 7)  ? 0.10936072f
         : (k == 4 || k == 6)  ? 0.21300555f
         : (k == 5)            ? 0.26601173f
         : 0.0f;
}

// One horizontal-conv row: 4 cols from basec, store into smem row `hr`.
__device__ __forceinline__ void hconv_row(
    const float* __restrict__ Xi, const float* __restrict__ Yi,
    u64* __restrict__ sh_mu, u64* __restrict__ sh_sq, float* __restrict__ sh_xy,
    const int r0, const int hr, const int basec, const int q1) {
    const int gr = r0 + hr;
    const float* __restrict__ xr = Xi + (long)gr * 512;
    const float* __restrict__ yr = Yi + (long)gr * 512;
    const bool rok = (gr < 512);
    float xv[16], yv[16];
#pragma unroll
    for (int q = 0; q < 4; q++) {
        const int qc = basec + 4 * q;
        float4 xq, yq;
        if (rok && qc < 512) {
            xq = *reinterpret_cast<const float4*>(xr + qc);
            yq = *reinterpret_cast<const float4*>(yr + qc);
        } else {
            xq = make_float4(0.f, 0.f, 0.f, 0.f);
            yq = make_float4(0.f, 0.f, 0.f, 0.f);
        }
        xv[4 * q + 0] = xq.x; xv[4 * q + 1] = xq.y;
        xv[4 * q + 2] = xq.z; xv[4 * q + 3] = xq.w;
        yv[4 * q + 0] = yq.x; yv[4 * q + 1] = yq.y;
        yv[4 * q + 2] = yq.z; yv[4 * q + 3] = yq.w;
    }
    float ax[4], ay[4], axx[4], ayy[4], axy[4];
#pragma unroll
    for (int j = 0; j < 4; j++) {
        ax[j] = 0.f; ay[j] = 0.f; axx[j] = 0.f; ayy[j] = 0.f; axy[j] = 0.f;
    }
#pragma unroll
    for (int t = 0; t < 14; t++) {
        const float xt = xv[t], yt = yv[t];
        const float pxx = xt * xt;
        const float pyy = yt * yt;
        const float pxy = xt * yt;
#pragma unroll
        for (int j = 0; j < 4; j++) {
            const int k = t - j;
            if (k >= 0 && k <= 10) {
                fmaw(k, xt,  ax[j]);
                fmaw(k, yt,  ay[j]);
                fmaw(k, pxx, axx[j]);
                fmaw(k, pyy, ayy[j]);
                fmaw(k, pxy, axy[j]);
            }
        }
    }
    // Pair at store time only: {hx,hy} and {hxx,hyy} interleaved planes.
    const int so = hr * TW + 4 * q1;
    *reinterpret_cast<ulonglong2*>(&sh_mu[so]) =
        make_ulonglong2(pk2(ax[0], ay[0]), pk2(ax[1], ay[1]));
    *reinterpret_cast<ulonglong2*>(&sh_mu[so + 2]) =
        make_ulonglong2(pk2(ax[2], ay[2]), pk2(ax[3], ay[3]));
    *reinterpret_cast<ulonglong2*>(&sh_sq[so]) =
        make_ulonglong2(pk2(axx[0], ayy[0]), pk2(axx[1], ayy[1]));
    *reinterpret_cast<ulonglong2*>(&sh_sq[so + 2]) =
        make_ulonglong2(pk2(axx[2], ayy[2]), pk2(axx[3], ayy[3]));
    *reinterpret_cast<float4*>(&sh_xy[so]) =
        make_float4(axy[0], axy[1], axy[2], axy[3]);
}

__global__ void __launch_bounds__(NTHR, 4)
ssim_main_kernel(const float* __restrict__ X, const float* __restrict__ Y,
                 float* __restrict__ out, double inv_count) {
    extern __shared__ char shb[];
    u64*   sh_mu = reinterpret_cast<u64*>(shb + MU_OFF);   // [NHR][TW] {hx,hy}
    u64*   sh_sq = reinterpret_cast<u64*>(shb + SQ_OFF);   // [NHR][TW] {hxx,hyy}
    float* sh_xy = reinterpret_cast<float*>(shb + XY_OFF); // [NHR][TW] hxy

    const int tid = threadIdx.x;
    const int c0 = blockIdx.x * TW;
    const int r0 = blockIdx.y * TH;
    const long img = blockIdx.z;
    const float* __restrict__ Xi = X + img * (512L * 512L);
    const float* __restrict__ Yi = Y + img * (512L * 512L);

    // ---------------- Phase 1: statically peeled (2 + 1 predicated iters) -------
    {
        const int q1 = tid & 7;
        const int r1 = tid >> 3;   // 0..31
        const int basec = c0 + 4 * q1;
        hconv_row(Xi, Yi, sh_mu, sh_sq, sh_xy, r0, r1,      basec, q1);
        hconv_row(Xi, Yi, sh_mu, sh_sq, sh_xy, r0, r1 + 32, basec, q1);
        if (r1 < NHR - 64)   // rows 64..73
            hconv_row(Xi, Yi, sh_mu, sh_sq, sh_xy, r0, r1 + 64, basec, q1);
    }
    __syncthreads();

    // ---------------- Phase 2: vertical conv, 3 LDS per tap, all fma2 -----------
    // Map B: 16 col-pairs x 16 row-groups (4 vrows each).
    const int tx2 = tid & 15;
    const int ty2 = tid >> 4;
    const int lr0 = ty2 * 4;
    const int scol = 2 * tx2;

    u64 WB[6];
#pragma unroll
    for (int k = 0; k < 6; k++) WB[k] = pk2(gwe(k), gwe(k));

    u64 amu[4][2], asq[4][2], axy2[4];
#pragma unroll
    for (int v = 0; v < 4; v++) {
        amu[v][0] = 0ull; amu[v][1] = 0ull;
        asq[v][0] = 0ull; asq[v][1] = 0ull;
        axy2[v] = 0ull;
    }

#pragma unroll
    for (int i = 0; i < 14; i++) {
        const int roff = (lr0 + i) * TW + scol;
        const ulonglong2 m = *reinterpret_cast<const ulonglong2*>(&sh_mu[roff]);
        const ulonglong2 s = *reinterpret_cast<const ulonglong2*>(&sh_sq[roff]);
        const u64 xp = *reinterpret_cast<const u64*>(&sh_xy[roff]);
#pragma unroll
        for (int v = 0; v < 4; v++) {
            const int k = i - v;
            if (k >= 0 && k <= 10) {
                const u64 w = WB[k <= 5 ? k : 10 - k];
                amu[v][0] = fma2(m.x, w, amu[v][0]);
                amu[v][1] = fma2(m.y, w, amu[v][1]);
                asq[v][0] = fma2(s.x, w, asq[v][0]);
                asq[v][1] = fma2(s.y, w, asq[v][1]);
                axy2[v]   = fma2(xp,  w, axy2[v]);
            }
        }
    }

    // ---------------- Epilogue + reduction ----------------
    float lsum = 0.0f;
    const float C1 = 1e-4f;      // (0.01)^2
    const float C2x4 = 0.0036f;  // 4*(0.03)^2
#pragma unroll
    for (int v = 0; v < 4; v++) {
        const int orow = r0 + lr0 + v;
        float xyc0, xyc1;
        upk2(xyc0, xyc1, axy2[v]);
#pragma unroll
        for (int c = 0; c < 2; c++) {
            const int ocol = c0 + scol + c;
            float m1, m2, xx, yy;
            upk2(m1, m2, amu[v][c]);
            upk2(xx, yy, asq[v][c]);
            const float xy = c ? xyc1 : xyc0;
            const float s1  = fmaf(-m1, m1, xx);
            const float s2  = fmaf(-m2, m2, yy);
            const float s12 = fmaf(-m1, m2, xy);
            const float m1p = fmaf(0.5f, m1, 0.5f);
            const float m2p = fmaf(0.5f, m2, 0.5f);
            const float csn = fmaf(2.0f, s12, C2x4);
            const float csd = s1 + s2 + C2x4;
            const float t = m1p * m2p;
            const float ln = fmaf(2.0f, t, C1);
            const float ld = fmaf(m1p, m1p, fmaf(m2p, m2p, C1));
            const float ssim = (csn * ln) * __fdividef(1.0f, csd * ld);
            lsum += (orow < 502 && ocol < 502) ? ssim : 0.0f;
        }
    }

#pragma unroll
    for (int off = 16; off > 0; off >>= 1)
        lsum += __shfl_xor_sync(0xffffffffu, lsum, off);

    __shared__ float wsum[8];
    __shared__ bool is_last;
    const int wid = tid >> 5;
    const int lid = tid & 31;
    if (lid == 0) wsum[wid] = lsum;
    __syncthreads();
    if (tid == 0) {
        float b = 0.0f;
#pragma unroll
        for (int w = 0; w < 8; w++) b += wsum[w];
        const int bi = blockIdx.x + gridDim.x * (blockIdx.y + gridDim.y * blockIdx.z);
        g_partials[bi] = b;
        __threadfence();
        const unsigned int n = atomicAdd(&g_count, 1u);
        is_last = (n == (unsigned int)(NBLOCKS - 1));
    }
    __syncthreads();

    if (is_last) {
        __threadfence();
        double s = 0.0;
        for (int i = tid; i < NBLOCKS; i += NTHR)
            s += (double)g_partials[i];
#pragma unroll
        for (int off = 16; off > 0; off >>= 1)
            s += __shfl_xor_sync(0xffffffffu, s, off);
        __shared__ double sd[8];
        if (lid == 0) sd[wid] = s;
        __syncthreads();
        if (tid == 0) {
            double tot = 0.0;
#pragma unroll
            for (int w = 0; w < 8; w++) tot += sd[w];
            out[0] = (float)(tot * inv_count);
            g_count = 0;  // reset for next graph replay
        }
    }
}

extern "C" void kernel_launch(void* const* d_in, const int* in_sizes, int n_in,
                              void* d_out, int out_size) {
    const float* X = (const float*)d_in[0];
    const float* Y = (const float*)d_in[1];
    float* out = (float*)d_out;

    const int images = in_sizes[0] / (512 * 512);  // 96
    const double count = (double)images * 502.0 * 502.0;

    cudaFuncSetAttribute(ssim_main_kernel,
                         cudaFuncAttributeMaxDynamicSharedMemorySize, SMEM_BYTES);

    dim3 grid(GX, GY, images);  // 16 x 8 x 96 = 12288 blocks
    ssim_main_kernel<<<grid, NTHR, SMEM_BYTES>>>(X, Y, out, 1.0 / count);
}

// round 14
// speedup vs baseline: 1.1633x; 1.1009x over previous
#include <cuda_runtime.h>

// SSIM, fully fused, single kernel. X,Y: f32[32,3,512,512] -> scalar mean SSIM.
//
// Sum/difference transform: s=x+y, d=x-y. SSIM needs only symmetric moment
// combinations, so ONLY 4 fields are convolved: {s, d, s^2, d^2} (was 5).
//   mu1*mu2, mu1^2+mu2^2      <- mu_s^2, mu_d^2
//   sigma1^2+sigma2^2, sigma12 <- var_s = E[s^2]-mu_s^2, var_d = E[d^2]-mu_d^2
// -20% conv fma in phase 2, -11% in phase 1, -20% smem traffic.
//
// TW=32 x TH=64, smem planes mu u64[74][32] {h_s,h_d}, sq u64[74][32]
// {h_ss,h_dd} = 37.9KB -> 4 CTAs/SM (32 warps), <=64 regs/thread.
// Phase 1 (8 col-quads x 32 rows, statically peeled 2+1 iters): horizontal
//   11-tap Gaussian, scalar FFMA-imm (rt=1); pairs packed at store only.
// Phase 2 (16 col-pairs x 16 row-groups, 4 vrows x 2 cols): vertical conv,
//   2x LDS.128 per tap, all fma.rn.f32x2, static smem offsets.
// Epilogue (folded [-1,1]->[0,1]): T = mu_s/2 + 0.5 + C1; A=mu_s^2, B=mu_d^2;
//   ln=(A-B)/8+T, ld=(A+B)/8+T; P=Ess-A, Q=Edd-B;
//   cs = (P-Q+8C2)/(P+Q+8C2); ssim = cs * ln/ld.
// Block partials -> __device__ array; last block reduces, writes scalar, resets.

#define TW 32
#define TH 64
#define NHR (TH + 10)   // 74
#define NTHR 256
#define GX 16
#define GY 8
#define GZ 96
#define NBLOCKS (GX * GY * GZ)

#define MU_OFF 0
#define SQ_OFF (NHR * TW * 8)          // 18944
#define SMEM_BYTES (2 * NHR * TW * 8)  // 37888

typedef unsigned long long u64;

__device__ float g_partials[NBLOCKS];
__device__ unsigned int g_count = 0;

// scalar: acc += v * w[k], w[k] immediate multiplier (FFMA-imm, rt=1).
__device__ __forceinline__ void fmaw(const int k, const float v, float& a) {
    switch (k) {
    case 0:  asm("fma.rn.f32 %0, %1, 0f3A86CAB5, %0;" : "+f"(a) : "f"(v)); break;
    case 1:  asm("fma.rn.f32 %0, %1, 0f3BF8FF05, %0;" : "+f"(a) : "f"(v)); break;
    case 2:  asm("fma.rn.f32 %0, %1, 0f3D137590, %0;" : "+f"(a) : "f"(v)); break;
    case 3:  asm("fma.rn.f32 %0, %1, 0f3DDFF883, %0;" : "+f"(a) : "f"(v)); break;
    case 4:  asm("fma.rn.f32 %0, %1, 0f3E5A1E20, %0;" : "+f"(a) : "f"(v)); break;
    case 5:  asm("fma.rn.f32 %0, %1, 0f3E8832B1, %0;" : "+f"(a) : "f"(v)); break;
    case 6:  asm("fma.rn.f32 %0, %1, 0f3E5A1E20, %0;" : "+f"(a) : "f"(v)); break;
    case 7:  asm("fma.rn.f32 %0, %1, 0f3DDFF883, %0;" : "+f"(a) : "f"(v)); break;
    case 8:  asm("fma.rn.f32 %0, %1, 0f3D137590, %0;" : "+f"(a) : "f"(v)); break;
    case 9:  asm("fma.rn.f32 %0, %1, 0f3BF8FF05, %0;" : "+f"(a) : "f"(v)); break;
    case 10: asm("fma.rn.f32 %0, %1, 0f3A86CAB5, %0;" : "+f"(a) : "f"(v)); break;
    default: break;
    }
}

__device__ __forceinline__ u64 pk2(float lo, float hi) {
    u64 r;
    asm("mov.b64 %0, {%1, %2};" : "=l"(r) : "f"(lo), "f"(hi));
    return r;
}
__device__ __forceinline__ void upk2(float& lo, float& hi, u64 v) {
    asm("mov.b64 {%0, %1}, %2;" : "=f"(lo), "=f"(hi) : "l"(v));
}
__device__ __forceinline__ u64 fma2(u64 a, u64 b, u64 c) {
    u64 d;
    asm("fma.rn.f32x2 %0, %1, %2, %3;" : "=l"(d) : "l"(a), "l"(b), "l"(c));
    return d;
}

// Gaussian(11, sigma=1.5) weights.
__device__ __host__ __forceinline__ constexpr float gwe(int k) {
    return (k == 0 || k == 10) ? 0.00102838f
         : (k == 1 || k == 9)  ? 0.00759876f
         : (k == 2 || k == 8)  ? 0.03600079f
         : (k == 3 || k == 7)  ? 0.10936072f
         : (k == 4 || k == 6)  ? 0.21300555f
         : (k == 5)            ? 0.26601173f
         : 0.0f;
}

// One horizontal-conv row: 4 cols from basec, store into smem row `hr`.
__device__ __forceinline__ void hconv_row(
    const float* __restrict__ Xi, const float* __restrict__ Yi,
    u64* __restrict__ sh_mu, u64* __restrict__ sh_sq,
    const int r0, const int hr, const int basec, const int q1) {
    const int gr = r0 + hr;
    const float* __restrict__ xr = Xi + (long)gr * 512;
    const float* __restrict__ yr = Yi + (long)gr * 512;
    const bool rok = (gr < 512);
    float xv[16], yv[16];
#pragma unroll
    for (int q = 0; q < 4; q++) {
        const int qc = basec + 4 * q;
        float4 xq, yq;
        if (rok && qc < 512) {
            xq = *reinterpret_cast<const float4*>(xr + qc);
            yq = *reinterpret_cast<const float4*>(yr + qc);
        } else {
            xq = make_float4(0.f, 0.f, 0.f, 0.f);
            yq = make_float4(0.f, 0.f, 0.f, 0.f);
        }
        xv[4 * q + 0] = xq.x; xv[4 * q + 1] = xq.y;
        xv[4 * q + 2] = xq.z; xv[4 * q + 3] = xq.w;
        yv[4 * q + 0] = yq.x; yv[4 * q + 1] = yq.y;
        yv[4 * q + 2] = yq.z; yv[4 * q + 3] = yq.w;
    }
    float as[4], ad[4], ass[4], add[4];
#pragma unroll
    for (int j = 0; j < 4; j++) {
        as[j] = 0.f; ad[j] = 0.f; ass[j] = 0.f; add[j] = 0.f;
    }
#pragma unroll
    for (int t = 0; t < 14; t++) {
        const float st = xv[t] + yv[t];
        const float dt = xv[t] - yv[t];
        const float sst = st * st;
        const float ddt = dt * dt;
#pragma unroll
        for (int j = 0; j < 4; j++) {
            const int k = t - j;
            if (k >= 0 && k <= 10) {
                fmaw(k, st,  as[j]);
                fmaw(k, dt,  ad[j]);
                fmaw(k, sst, ass[j]);
                fmaw(k, ddt, add[j]);
            }
        }
    }
    // Pair at store time only: {h_s,h_d} and {h_ss,h_dd} interleaved planes.
    const int so = hr * TW + 4 * q1;
    *reinterpret_cast<ulonglong2*>(&sh_mu[so]) =
        make_ulonglong2(pk2(as[0], ad[0]), pk2(as[1], ad[1]));
    *reinterpret_cast<ulonglong2*>(&sh_mu[so + 2]) =
        make_ulonglong2(pk2(as[2], ad[2]), pk2(as[3], ad[3]));
    *reinterpret_cast<ulonglong2*>(&sh_sq[so]) =
        make_ulonglong2(pk2(ass[0], add[0]), pk2(ass[1], add[1]));
    *reinterpret_cast<ulonglong2*>(&sh_sq[so + 2]) =
        make_ulonglong2(pk2(ass[2], add[2]), pk2(ass[3], add[3]));
}

__global__ void __launch_bounds__(NTHR, 4)
ssim_main_kernel(const float* __restrict__ X, const float* __restrict__ Y,
                 float* __restrict__ out, double inv_count) {
    extern __shared__ char shb[];
    u64* sh_mu = reinterpret_cast<u64*>(shb + MU_OFF);  // [NHR][TW] {h_s,h_d}
    u64* sh_sq = reinterpret_cast<u64*>(shb + SQ_OFF);  // [NHR][TW] {h_ss,h_dd}

    const int tid = threadIdx.x;
    const int c0 = blockIdx.x * TW;
    const int r0 = blockIdx.y * TH;
    const long img = blockIdx.z;
    const float* __restrict__ Xi = X + img * (512L * 512L);
    const float* __restrict__ Yi = Y + img * (512L * 512L);

    // ---------------- Phase 1: statically peeled (2 + 1 predicated iters) -------
    {
        const int q1 = tid & 7;
        const int r1 = tid >> 3;   // 0..31
        const int basec = c0 + 4 * q1;
        hconv_row(Xi, Yi, sh_mu, sh_sq, r0, r1,      basec, q1);
        hconv_row(Xi, Yi, sh_mu, sh_sq, r0, r1 + 32, basec, q1);
        if (r1 < NHR - 64)   // rows 64..73
            hconv_row(Xi, Yi, sh_mu, sh_sq, r0, r1 + 64, basec, q1);
    }
    __syncthreads();

    // ---------------- Phase 2: vertical conv, 2x LDS.128 per tap, all fma2 ------
    // Map B: 16 col-pairs x 16 row-groups (4 vrows each).
    const int tx2 = tid & 15;
    const int ty2 = tid >> 4;
    const int lr0 = ty2 * 4;
    const int scol = 2 * tx2;

    u64 WB[6];
#pragma unroll
    for (int k = 0; k < 6; k++) WB[k] = pk2(gwe(k), gwe(k));

    u64 amu[4][2], asq[4][2];   // [vrow][col] {s,d} / {ss,dd}
#pragma unroll
    for (int v = 0; v < 4; v++) {
        amu[v][0] = 0ull; amu[v][1] = 0ull;
        asq[v][0] = 0ull; asq[v][1] = 0ull;
    }

#pragma unroll
    for (int i = 0; i < 14; i++) {
        const int roff = (lr0 + i) * TW + scol;
        const ulonglong2 m = *reinterpret_cast<const ulonglong2*>(&sh_mu[roff]);
        const ulonglong2 s = *reinterpret_cast<const ulonglong2*>(&sh_sq[roff]);
#pragma unroll
        for (int v = 0; v < 4; v++) {
            const int k = i - v;
            if (k >= 0 && k <= 10) {
                const u64 w = WB[k <= 5 ? k : 10 - k];
                amu[v][0] = fma2(m.x, w, amu[v][0]);
                amu[v][1] = fma2(m.y, w, amu[v][1]);
                asq[v][0] = fma2(s.x, w, asq[v][0]);
                asq[v][1] = fma2(s.y, w, asq[v][1]);
            }
        }
    }

    // ---------------- Epilogue + reduction ----------------
    // Raw-unit algebra (x,y in [-1,1]); normalization folded:
    //   A = mu_s^2, B = mu_d^2; T = mu_s/2 + 0.5 + C1
    //   ln = (A-B)/8 + T;  ld = (A+B)/8 + T
    //   P = E[ss]-A; Q = E[dd]-B;  cs = (P-Q+8C2)/(P+Q+8C2)
    float lsum = 0.0f;
    const float TC = 0.5f + 1e-4f;   // 0.5 + C1
    const float C2x8 = 0.0072f;      // 8*(0.03)^2
#pragma unroll
    for (int v = 0; v < 4; v++) {
        const int orow = r0 + lr0 + v;
#pragma unroll
        for (int c = 0; c < 2; c++) {
            const int ocol = c0 + scol + c;
            float ms, md, ess, edd;
            upk2(ms, md, amu[v][c]);
            upk2(ess, edd, asq[v][c]);
            const float A = ms * ms;
            const float B = md * md;
            const float P = ess - A;
            const float Q = edd - B;
            const float T = fmaf(0.5f, ms, TC);
            const float A8 = 0.125f * A;
            const float B8 = 0.125f * B;
            const float ln = (A8 - B8) + T;
            const float ld = (A8 + B8) + T;
            const float csn = (P - Q) + C2x8;
            const float csd = (P + Q) + C2x8;
            const float ssim = (csn * ln) * __fdividef(1.0f, csd * ld);
            lsum += (orow < 502 && ocol < 502) ? ssim : 0.0f;
        }
    }

#pragma unroll
    for (int off = 16; off > 0; off >>= 1)
        lsum += __shfl_xor_sync(0xffffffffu, lsum, off);

    __shared__ float wsum[8];
    __shared__ bool is_last;
    const int wid = tid >> 5;
    const int lid = tid & 31;
    if (lid == 0) wsum[wid] = lsum;
    __syncthreads();
    if (tid == 0) {
        float b = 0.0f;
#pragma unroll
        for (int w = 0; w < 8; w++) b += wsum[w];
        const int bi = blockIdx.x + gridDim.x * (blockIdx.y + gridDim.y * blockIdx.z);
        g_partials[bi] = b;
        __threadfence();
        const unsigned int n = atomicAdd(&g_count, 1u);
        is_last = (n == (unsigned int)(NBLOCKS - 1));
    }
    __syncthreads();

    if (is_last) {
        __threadfence();
        double s = 0.0;
        for (int i = tid; i < NBLOCKS; i += NTHR)
            s += (double)g_partials[i];
#pragma unroll
        for (int off = 16; off > 0; off >>= 1)
            s += __shfl_xor_sync(0xffffffffu, s, off);
        __shared__ double sd[8];
        if (lid == 0) sd[wid] = s;
        __syncthreads();
        if (tid == 0) {
            double tot = 0.0;
#pragma unroll
            for (int w = 0; w < 8; w++) tot += sd[w];
            out[0] = (float)(tot * inv_count);
            g_count = 0;  // reset for next graph replay
        }
    }
}

extern "C" void kernel_launch(void* const* d_in, const int* in_sizes, int n_in,
                              void* d_out, int out_size) {
    const float* X = (const float*)d_in[0];
    const float* Y = (const float*)d_in[1];
    float* out = (float*)d_out;

    const int images = in_sizes[0] / (512 * 512);  // 96
    const double count = (double)images * 502.0 * 502.0;

    cudaFuncSetAttribute(ssim_main_kernel,
                         cudaFuncAttributeMaxDynamicSharedMemorySize, SMEM_BYTES);

    dim3 grid(GX, GY, images);  // 16 x 8 x 96 = 12288 blocks
    ssim_main_kernel<<<grid, NTHR, SMEM_BYTES>>>(X, Y, out, 1.0 / count);
}